// round 15
// baseline (speedup 1.0000x reference)
#include <cuda_runtime.h>

// PrefixSumCounts: counts[b,s] = #{t <= s : x[b,t] == x[b,s]}
// B=4, S=4096, V=32000 (fixed by this problem instance).
//
// ONE kernel, 64 independent blocks = B*CC chunks of 256; NO cross-block
// communication (validated in R14). Changes vs R14:
//   - histogram is u16-PACKED (two counts per u32 word): SMEM zero halves
//     to 64KB (~512cyc floor), atomicAdd(word, 1<<((v&1)*16)); prefix
//     counts <= 4096 so halfwords never overflow.
//   - 512 threads/block: threads 256..511 are SCAN HELPERS (position p's
//     earlier-warp range [0,8w) int4 splits in half between thread p and
//     p+256, warp-uniform bounds), and histogram loads/atomics spread over
//     2x threads -> 16 warps/SM of latency hiding.
//   - scan loops #pragma unroll 4 to pipeline LDS.

#define BB 4
#define SS 4096
#define CC 16
#define LL 256               // positions per chunk
#define NBLK (BB * CC)       // 64
#define THREADS 512
#define VS 32768             // >= vocab 32000
#define HWORDS (VS / 2)      // packed u32 words
// hist 64KB + xs 1KB + part 1KB
#define SMEM_BYTES (HWORDS * 4 + LL * 4 + LL * 4)

__global__ void __launch_bounds__(THREADS, 1) counts_kernel(
    const int* __restrict__ x, float* __restrict__ out)
{
    extern __shared__ unsigned int smem[];
    unsigned int* hist = smem;                      // [HWORDS] packed u16x2
    int* xs   = reinterpret_cast<int*>(smem + HWORDS);      // [LL]
    int* part = xs + LL;                                     // [LL]

    const int t = threadIdx.x;
    const int c = blockIdx.x & (CC - 1);
    const int b = blockIdx.x >> 4;

    // ---- issue all global loads first (hide L2/DRAM latency) ----
    int v = 0;
    if (t < LL) v = __ldg(&x[blockIdx.x * LL + t]);

    const int4* xrow4 = reinterpret_cast<const int4*>(x + b * SS);
    const int nvec4 = c * (LL / 4);                 // int4s covering chunks < c
    int4 q0, q1;
    int nq = 0;
    if (t < nvec4)           { q0 = __ldg(&xrow4[t]);           nq = 1; }
    if (t + THREADS < nvec4) { q1 = __ldg(&xrow4[t + THREADS]); nq = 2; }

    if (t < LL) xs[t] = v;

    // ---- zero packed histogram: 64KB, 8 int4 stores per thread ----
    int4* h4 = reinterpret_cast<int4*>(hist);
#pragma unroll
    for (int i = 0; i < (HWORDS / 4) / THREADS; ++i)
        h4[t + i * THREADS] = make_int4(0, 0, 0, 0);
    __syncthreads();

    // ---- histogram earlier chunks (packed halfword atomics, spread) ----
    if (nq > 0) {
        atomicAdd(&hist[(unsigned)q0.x >> 1], 1u << ((q0.x & 1) << 4));
        atomicAdd(&hist[(unsigned)q0.y >> 1], 1u << ((q0.y & 1) << 4));
        atomicAdd(&hist[(unsigned)q0.z >> 1], 1u << ((q0.z & 1) << 4));
        atomicAdd(&hist[(unsigned)q0.w >> 1], 1u << ((q0.w & 1) << 4));
    }
    if (nq > 1) {
        atomicAdd(&hist[(unsigned)q1.x >> 1], 1u << ((q1.x & 1) << 4));
        atomicAdd(&hist[(unsigned)q1.y >> 1], 1u << ((q1.y & 1) << 4));
        atomicAdd(&hist[(unsigned)q1.z >> 1], 1u << ((q1.z & 1) << 4));
        atomicAdd(&hist[(unsigned)q1.w >> 1], 1u << ((q1.w & 1) << 4));
    }

    // ---- within-chunk rank, split across thread pairs ----
    const int4* xs4 = reinterpret_cast<const int4*>(xs);
    int myrank = 0;
    if (t < LL) {
        const int w = t >> 5;
        const int lo = w << 2, hi = w << 3;        // my half: [4w, 8w)
#pragma unroll 4
        for (int j = lo; j < hi; ++j) {
            const int4 q = xs4[j];
            myrank += (q.x == v) + (q.y == v) + (q.z == v) + (q.w == v);
        }
        const unsigned int mm = __match_any_sync(0xffffffffu, v);
        myrank += __popc(mm & ((1u << (t & 31)) - 1u));
    } else {
        const int p = t - LL;                      // helper for position p
        const int pv = xs[p];                      // safe: xs synced above
        const int hi = (p >> 5) << 2;              // helper half: [0, 4w)
        int r = 0;
#pragma unroll 4
        for (int j = 0; j < hi; ++j) {
            const int4 q = xs4[j];
            r += (q.x == pv) + (q.y == pv) + (q.z == pv) + (q.w == pv);
        }
        part[p] = r;
    }
    __syncthreads();                               // atomics + part complete

    // ---- gather packed count, single store ----
    if (t < LL) {
        const unsigned int word = hist[(unsigned)v >> 1];
        const int base = (int)((word >> ((v & 1) << 4)) & 0xffffu);
        out[blockIdx.x * LL + t] = (float)(myrank + 1 + part[t] + base);
    }
}

extern "C" void kernel_launch(void* const* d_in, const int* in_sizes, int n_in,
                              void* d_out, int out_size) {
    (void)in_sizes; (void)n_in; (void)out_size;
    const int* x = (const int*)d_in[0];
    float* out = (float*)d_out;

    static bool attr_set = false;                  // host-side config only
    if (!attr_set) {
        cudaFuncSetAttribute(counts_kernel,
                             cudaFuncAttributeMaxDynamicSharedMemorySize,
                             SMEM_BYTES);
        attr_set = true;
    }
    counts_kernel<<<NBLK, THREADS, SMEM_BYTES>>>(x, out);
}